// round 8
// baseline (speedup 1.0000x reference)
#include <cuda_runtime.h>
#include <cstdint>

#define BB        4
#define NPTS      4096
#define TPB       1024
#define QPT       4                       // queries per thread (2 packed pairs)
#define QPB       (TPB * QPT)             // 4096 queries per block = one (dir,b)
#define NSLICE    16                      // target slices
#define SLICE_PTS (NPTS / NSLICE)         // 256 targets per slice
#define NQ_TOTAL  (2 * BB * NPTS)         // 32768 query slots
#define NQTILE    (NQ_TOTAL / QPB)        // 8  (= dir*4 + b)
#define NBLK1     (NQTILE * NSLICE)       // 128 blocks, 1/SM, 8 warps/SMSP

// Per-query running min as float BIT PATTERN (distances > 0 -> uint order ==
// float order). memset to 0x7F7F7F7F (3.39e38) each launch. atomicMin is exact
// and idempotent -> bit-deterministic.
__device__ unsigned g_minq[NQ_TOTAL];     // 128 KB
__device__ int      g_ticket;             // zero-init; last block resets it

__device__ __forceinline__ uint64_t pk2(float lo, float hi) {
    uint64_t r;
    asm("mov.b64 %0, {%1, %2};" : "=l"(r) : "f"(lo), "f"(hi));
    return r;
}
__device__ __forceinline__ uint64_t fma2(uint64_t a, uint64_t b, uint64_t c) {
    uint64_t d;
    asm("fma.rn.f32x2 %0, %1, %2, %3;" : "=l"(d) : "l"(a), "l"(b), "l"(c));
    return d;
}
__device__ __forceinline__ void unpk(uint64_t v, float& lo, float& hi) {
    asm("mov.b64 {%0, %1}, %2;" : "=f"(lo), "=f"(hi) : "l"(v));
}

// Block = (4096-query tile = one (dir,batch)) x (256-target slice), 1024 threads.
// Targets BROADCAST-DUPLICATED in smem: sT1[p]={x,x,y,y}, sT2[p]={z,z,w,w}, w=|t|^2.
// Queries packed in PAIRS: QX[j]={-2sx_a,-2sx_b}. Per target step per thread:
// 2 LDS.128 + 6 FFMA2 + 4 FMNMX (4 distances). 8 warps/SMSP hide the latency.
__global__ void __launch_bounds__(TPB, 1)
chamfer_fused(const float* __restrict__ src, const float* __restrict__ tgt,
              float* __restrict__ out)
{
    __shared__ float4 sT1[SLICE_PTS];   // {tx,tx,ty,ty}
    __shared__ float4 sT2[SLICE_PTS];   // {tz,tz, w, w}

    int qtile = blockIdx.x >> 4;          // 0..7 = dir*4 + b
    int slice = blockIdx.x & 15;
    int dir   = qtile >> 2;
    int b     = qtile & 3;

    const float* qb = (dir ? tgt : src) + (size_t)b * NPTS * 3;
    const float* db = (dir ? src : tgt) + ((size_t)b * NPTS + slice * SLICE_PTS) * 3;

    if (threadIdx.x < SLICE_PTS) {
        int p = threadIdx.x;
        float x = db[3 * p], y = db[3 * p + 1], z = db[3 * p + 2];
        float w = fmaf(x, x, fmaf(y, y, z * z));
        sT1[p] = make_float4(x, x, y, y);
        sT2[p] = make_float4(z, z, w, w);
    }

    // 2 packed query pairs: pair j = queries (tid + 2j*TPB, tid + (2j+1)*TPB).
    uint64_t QX[2], QY[2], QZ[2];
    float x2lo[2], x2hi[2], mlo[2], mhi[2];
    #pragma unroll
    for (int j = 0; j < 2; j++) {
        int qa = threadIdx.x + (2 * j) * TPB;
        int qc = threadIdx.x + (2 * j + 1) * TPB;
        float ax = qb[3 * qa], ay = qb[3 * qa + 1], az = qb[3 * qa + 2];
        float cx = qb[3 * qc], cy = qb[3 * qc + 1], cz = qb[3 * qc + 2];
        x2lo[j] = fmaf(ax, ax, fmaf(ay, ay, az * az));
        x2hi[j] = fmaf(cx, cx, fmaf(cy, cy, cz * cz));
        QX[j] = pk2(-2.f * ax, -2.f * cx);
        QY[j] = pk2(-2.f * ay, -2.f * cy);
        QZ[j] = pk2(-2.f * az, -2.f * cz);
        mlo[j] = 3.4e38f; mhi[j] = 3.4e38f;
    }
    __syncthreads();

    const ulonglong2* T1 = (const ulonglong2*)sT1;  // .x={tx,tx} .y={ty,ty}
    const ulonglong2* T2 = (const ulonglong2*)sT2;  // .x={tz,tz} .y={ w, w}

    #pragma unroll 8
    for (int p = 0; p < SLICE_PTS; p++) {
        ulonglong2 t1 = T1[p];
        ulonglong2 t2 = T2[p];
        #pragma unroll
        for (int j = 0; j < 2; j++) {
            uint64_t v = fma2(QX[j], t1.x, fma2(QY[j], t1.y, fma2(QZ[j], t2.x, t2.y)));
            float v0, v1;
            unpk(v, v0, v1);
            mlo[j] = fminf(mlo[j], v0);
            mhi[j] = fminf(mhi[j], v1);
        }
    }

    // Cross-slice combine: REDG.MIN on float bits.
    int gq0 = qtile * QPB + threadIdx.x;
    #pragma unroll
    for (int j = 0; j < 2; j++) {
        atomicMin(&g_minq[gq0 + (2 * j)     * TPB], __float_as_uint(mlo[j] + x2lo[j]));
        atomicMin(&g_minq[gq0 + (2 * j + 1) * TPB], __float_as_uint(mhi[j] + x2hi[j]));
    }

    // Ticket: last block performs the final sum.
    __threadfence();
    __syncthreads();
    __shared__ int amLast;
    if (threadIdx.x == 0) {
        int prev = atomicAdd(&g_ticket, 1);
        amLast = (prev == NBLK1 - 1);
    }
    __syncthreads();
    if (!amLast) return;

    __threadfence();   // acquire: all blocks' REDG.MINs visible
    float sum = 0.f;
    const uint4* G = (const uint4*)g_minq;            // 8192 uint4
    #pragma unroll
    for (int jj = 0; jj < NQ_TOTAL / 4 / TPB; jj++) { // 8 iters
        uint4 u = __ldcg(&G[threadIdx.x + jj * TPB]); // bypass L1 (atomics in L2)
        sum += (__uint_as_float(u.x) + __uint_as_float(u.y))
             + (__uint_as_float(u.z) + __uint_as_float(u.w));
    }
    #pragma unroll
    for (int off = 16; off > 0; off >>= 1)
        sum += __shfl_down_sync(0xFFFFFFFFu, sum, off);

    __shared__ float ws[TPB / 32];
    if ((threadIdx.x & 31) == 0) ws[threadIdx.x >> 5] = sum;
    __syncthreads();
    if (threadIdx.x == 0) {
        float tot = 0.f;
        #pragma unroll
        for (int i = 0; i < TPB / 32; i++) tot += ws[i];   // fixed order
        out[0] = tot * (1.0f / (float)(BB * NPTS));
        g_ticket = 0;                                      // reset for next replay
    }
}

extern "C" void kernel_launch(void* const* d_in, const int* in_sizes, int n_in,
                              void* d_out, int out_size)
{
    const float* src = (const float*)d_in[0];
    const float* tgt = (const float*)d_in[1];
    float* out = (float*)d_out;

    void* minq_addr = nullptr;
    cudaGetSymbolAddress(&minq_addr, g_minq);
    // 0x7F7F7F7F = 3.39e38f sentinel, far above any real squared distance.
    cudaMemsetAsync(minq_addr, 0x7F, NQ_TOTAL * sizeof(unsigned));

    chamfer_fused<<<NBLK1, TPB>>>(src, tgt, out);
}

// round 10
// speedup vs baseline: 1.1530x; 1.1530x over previous
#include <cuda_runtime.h>
#include <cstdint>

#define BB       4
#define NPTS     4096
#define TPB      512
#define NWARP    (TPB / 32)               // 16
#define NSLICE   32                       // target slices per batch
#define TSL      (NPTS / NSLICE)          // 128 targets per slice
#define NBLK1    (BB * NSLICE)            // 128 blocks, 1/SM
#define NQ_TOTAL (2 * BB * NPTS)          // 32768 min slots (16384 src + 16384 tgt)

// Running mins as float BIT PATTERNS (distances >= 0 -> uint order == float
// order). [0,16384): source-side (REDG.MIN, touched by 32 blocks).
// [16384,32768): target-side (plain STG, each owned by exactly 1 block).
__device__ unsigned g_minq[NQ_TOTAL];     // 128 KB
__device__ int      g_ticket;             // zero-init; last block resets it

__device__ __forceinline__ uint64_t pk2(float lo, float hi) {
    uint64_t r;
    asm("mov.b64 %0, {%1, %2};" : "=l"(r) : "f"(lo), "f"(hi));
    return r;
}
__device__ __forceinline__ uint64_t fma2(uint64_t a, uint64_t b, uint64_t c) {
    uint64_t d;
    asm("fma.rn.f32x2 %0, %1, %2, %3;" : "=l"(d) : "l"(a), "l"(b), "l"(c));
    return d;
}
__device__ __forceinline__ uint64_t add2(uint64_t a, uint64_t b) {
    uint64_t d;
    asm("add.rn.f32x2 %0, %1, %2;" : "=l"(d) : "l"(a), "l"(b));
    return d;
}
__device__ __forceinline__ void unpk(uint64_t v, float& lo, float& hi) {
    asm("mov.b64 {%0, %1}, %2;" : "=f"(lo), "=f"(hi) : "l"(v));
}

// SYMMETRIC kernel: each distance computed ONCE, feeds BOTH direction mins.
// Block = batch b x 128-target slice; all 4096 source points are the register
// queries (8/thread as 4 packed pairs). Per target step per thread:
//   2 LDS.128 + 12 FFMA2 + 4 ADD2 (full distance incl |q|^2)
//   + 8 FMNMX q-side packed mins + 7 FMNMX t-side fold (alu pipe, parallel).
// t-side: 8-target register window -> shfl-min tree -> sWT[warp][target]
// -> block-end fold over the 16 REAL warps -> STG. Min is exact => any
// reduction order is bit-identical.
__global__ void __launch_bounds__(TPB, 1)
chamfer_sym(const float* __restrict__ src, const float* __restrict__ tgt,
            float* __restrict__ out)
{
    __shared__ float4 sT1[TSL];           // {tx,tx,ty,ty}
    __shared__ float4 sT2[TSL];           // {tz,tz, w, w}  w=|t|^2
    __shared__ float  sWT[NWARP][TSL];    // per-warp t-side partial mins (8 KB)

    int b  = blockIdx.x >> 5;
    int tc = blockIdx.x & 31;
    int wid = threadIdx.x >> 5, lid = threadIdx.x & 31;

    const float* qb = src + (size_t)b * NPTS * 3;
    const float* db = tgt + ((size_t)b * NPTS + tc * TSL) * 3;

    if (threadIdx.x < TSL) {
        int p = threadIdx.x;
        float x = db[3 * p], y = db[3 * p + 1], z = db[3 * p + 2];
        float w = fmaf(x, x, fmaf(y, y, z * z));
        sT1[p] = make_float4(x, x, y, y);
        sT2[p] = make_float4(z, z, w, w);
    }

    // 4 packed query pairs; X2 packed so ADD2 gives the full distance.
    uint64_t QX[4], QY[4], QZ[4], X2[4];
    float mlo[4], mhi[4];
    #pragma unroll
    for (int j = 0; j < 4; j++) {
        int qa = threadIdx.x + (2 * j) * TPB;
        int qc = threadIdx.x + (2 * j + 1) * TPB;
        float ax = qb[3 * qa], ay = qb[3 * qa + 1], az = qb[3 * qa + 2];
        float cx = qb[3 * qc], cy = qb[3 * qc + 1], cz = qb[3 * qc + 2];
        X2[j] = pk2(fmaf(ax, ax, fmaf(ay, ay, az * az)),
                    fmaf(cx, cx, fmaf(cy, cy, cz * cz)));
        QX[j] = pk2(-2.f * ax, -2.f * cx);
        QY[j] = pk2(-2.f * ay, -2.f * cy);
        QZ[j] = pk2(-2.f * az, -2.f * cz);
        mlo[j] = 3.4e38f; mhi[j] = 3.4e38f;
    }
    __syncthreads();

    const ulonglong2* T1 = (const ulonglong2*)sT1;
    const ulonglong2* T2 = (const ulonglong2*)sT2;

    for (int po = 0; po < TSL / 8; po++) {        // 16 outer
        float W[8];
        #pragma unroll
        for (int pi = 0; pi < 8; pi++) {          // 8-target window
            int p = po * 8 + pi;
            ulonglong2 t1 = T1[p];
            ulonglong2 t2 = T2[p];
            float tmin;
            #pragma unroll
            for (int j = 0; j < 4; j++) {
                uint64_t v = fma2(QX[j], t1.x, fma2(QY[j], t1.y,
                                  fma2(QZ[j], t2.x, t2.y)));
                uint64_t d = add2(v, X2[j]);      // full distance (both sides)
                float d0, d1;
                unpk(d, d0, d1);
                mlo[j] = fminf(mlo[j], d0);       // q-side running mins
                mhi[j] = fminf(mhi[j], d1);
                float pmin = fminf(d0, d1);       // t-side fold over 8 queries
                tmin = (j == 0) ? pmin : fminf(tmin, pmin);
            }
            W[pi] = tmin;
        }
        // flush window: warp-min each of the 8 targets, lane0 -> sWT
        #pragma unroll
        for (int w = 0; w < 8; w++) {
            float v = W[w];
            #pragma unroll
            for (int off = 16; off > 0; off >>= 1)
                v = fminf(v, __shfl_down_sync(0xFFFFFFFFu, v, off));
            if (lid == 0) sWT[wid][po * 8 + w] = v;
        }
    }

    // q-side: REDG.MIN on bit patterns (exact & idempotent -> deterministic).
    int qg = b * NPTS + threadIdx.x;
    #pragma unroll
    for (int j = 0; j < 4; j++) {
        atomicMin(&g_minq[qg + (2 * j)     * TPB], __float_as_uint(mlo[j]));
        atomicMin(&g_minq[qg + (2 * j + 1) * TPB], __float_as_uint(mhi[j]));
    }

    // t-side: fold the 16 warp rows, plain store (unique owner per target).
    __syncthreads();
    if (threadIdx.x < TSL) {
        int p = threadIdx.x;
        float v = sWT[0][p];
        #pragma unroll
        for (int w = 1; w < NWARP; w++) v = fminf(v, sWT[w][p]);
        g_minq[NPTS * BB + b * NPTS + tc * TSL + p] = __float_as_uint(v);
    }

    // Ticket: last block sums everything.
    __threadfence();
    __syncthreads();
    __shared__ int amLast;
    if (threadIdx.x == 0) {
        int prev = atomicAdd(&g_ticket, 1);
        amLast = (prev == NBLK1 - 1);
    }
    __syncthreads();
    if (!amLast) return;

    __threadfence();   // acquire: all blocks' writes visible
    float sum = 0.f;
    const uint4* G = (const uint4*)g_minq;            // 8192 uint4
    #pragma unroll
    for (int jj = 0; jj < NQ_TOTAL / 4 / TPB; jj++) { // 16 iters
        uint4 u = __ldcg(&G[threadIdx.x + jj * TPB]);
        sum += (__uint_as_float(u.x) + __uint_as_float(u.y))
             + (__uint_as_float(u.z) + __uint_as_float(u.w));
    }
    #pragma unroll
    for (int off = 16; off > 0; off >>= 1)
        sum += __shfl_down_sync(0xFFFFFFFFu, sum, off);

    __shared__ float ws[TPB / 32];
    if ((threadIdx.x & 31) == 0) ws[threadIdx.x >> 5] = sum;
    __syncthreads();
    if (threadIdx.x == 0) {
        float tot = 0.f;
        #pragma unroll
        for (int i = 0; i < TPB / 32; i++) tot += ws[i];   // fixed order
        out[0] = tot * (1.0f / (float)(BB * NPTS));
        g_ticket = 0;                                      // reset for replay
    }
}

extern "C" void kernel_launch(void* const* d_in, const int* in_sizes, int n_in,
                              void* d_out, int out_size)
{
    const float* src = (const float*)d_in[0];
    const float* tgt = (const float*)d_in[1];
    float* out = (float*)d_out;

    void* minq_addr = nullptr;
    cudaGetSymbolAddress(&minq_addr, g_minq);
    // 0x7F7F7F7F = 3.39e38f sentinel for the REDG.MIN half.
    cudaMemsetAsync(minq_addr, 0x7F, NQ_TOTAL * sizeof(unsigned));

    chamfer_sym<<<NBLK1, TPB>>>(src, tgt, out);
}

// round 11
// speedup vs baseline: 1.2337x; 1.0700x over previous
#include <cuda_runtime.h>
#include <cstdint>

#define BB       4
#define NPTS     4096
#define TPB      512
#define NWARP    (TPB / 32)               // 16
#define NSLICE   32                       // target slices per batch
#define TSL      (NPTS / NSLICE)          // 128 targets per slice
#define TPR      (TSL / 2)                // 64 target pairs in smem
#define NBLK1    (BB * NSLICE)            // 128 blocks, 1/SM
#define NQ_TOTAL (2 * BB * NPTS)          // 32768 min slots (16384 src + 16384 tgt)

// Running mins as float BIT PATTERNS (distances >= 0 -> uint order == float
// order). [0,16384): source-side (REDG.MIN, touched by 32 blocks).
// [16384,32768): target-side (plain STG, each owned by exactly 1 block).
__device__ unsigned g_minq[NQ_TOTAL];     // 128 KB
__device__ int      g_ticket;             // zero-init; last block resets it

__device__ __forceinline__ uint64_t pk2(float lo, float hi) {
    uint64_t r;
    asm("mov.b64 %0, {%1, %2};" : "=l"(r) : "f"(lo), "f"(hi));
    return r;
}
__device__ __forceinline__ uint64_t fma2(uint64_t a, uint64_t b, uint64_t c) {
    uint64_t d;
    asm("fma.rn.f32x2 %0, %1, %2, %3;" : "=l"(d) : "l"(a), "l"(b), "l"(c));
    return d;
}
__device__ __forceinline__ uint64_t add2(uint64_t a, uint64_t b) {
    uint64_t d;
    asm("add.rn.f32x2 %0, %1, %2;" : "=l"(d) : "l"(a), "l"(b));
    return d;
}
__device__ __forceinline__ void unpk(uint64_t v, float& lo, float& hi) {
    asm("mov.b64 {%0, %1}, %2;" : "=f"(lo), "=f"(hi) : "l"(v));
}
// Butterfly fold step: this lane keeps the (sel ? odd : even) slot, gives the
// other away; partner (xor delta) does the mirror image. Returns min of kept
// and received values.
__device__ __forceinline__ float bfold(float even, float odd, int sel, int delta) {
    float give = sel ? even : odd;
    float recv = __shfl_xor_sync(0xFFFFFFFFu, give, delta);
    float keep = sel ? odd : even;
    return fminf(keep, recv);
}

// SYMMETRIC kernel: each distance computed ONCE, feeds BOTH direction mins.
// Targets PAIR-PACKED in smem (16 B per 2 targets): sP[p]={x0,x1,y0,y1},
// sQ[p]={z0,z1,w0,w1} (w=|t|^2). Queries duplicated in registers:
// QXd[q]={-2sx,-2sx}, X2d[q]={|s|^2,|s|^2}. Per target-pair step per thread:
//   2 LDS.128 + (8 queries x [1 ADD2 + 3 FFMA2]) -> 16 full distances
//   + 16 FMNMX q-side mins + 14 FMNMX t-side chains.
// t-side flush per 8-target window: 9-shfl butterfly (xor 1/2/4 register-
// halving + xor 8/16) -> lane&7 holds the warp-min -> sWT -> cross-warp fold.
// Min is exact => any reduction order is bit-identical.
__global__ void __launch_bounds__(TPB, 1)
chamfer_sym(const float* __restrict__ src, const float* __restrict__ tgt,
            float* __restrict__ out)
{
    __shared__ float4 sP[TPR];            // {x0,x1,y0,y1}
    __shared__ float4 sQ[TPR];            // {z0,z1,w0,w1}
    __shared__ float  sWT[NWARP][TSL];    // per-warp t-side partial mins (8 KB)

    int b   = blockIdx.x >> 5;
    int tc  = blockIdx.x & 31;
    int wid = threadIdx.x >> 5, lid = threadIdx.x & 31;

    const float* qb = src + (size_t)b * NPTS * 3;
    const float* db = tgt + ((size_t)b * NPTS + tc * TSL) * 3;

    if (threadIdx.x < TPR) {
        int p = threadIdx.x;
        const float* t = db + 6 * p;
        float x0 = t[0], y0 = t[1], z0 = t[2];
        float x1 = t[3], y1 = t[4], z1 = t[5];
        sP[p] = make_float4(x0, x1, y0, y1);
        sQ[p] = make_float4(z0, z1,
                            fmaf(x0, x0, fmaf(y0, y0, z0 * z0)),
                            fmaf(x1, x1, fmaf(y1, y1, z1 * z1)));
    }

    // 8 register queries, duplicated packs.
    uint64_t QXd[8], QYd[8], QZd[8], X2d[8];
    float qmin[8];
    #pragma unroll
    for (int q = 0; q < 8; q++) {
        int qa = threadIdx.x + q * TPB;
        float ax = qb[3 * qa], ay = qb[3 * qa + 1], az = qb[3 * qa + 2];
        float x2 = fmaf(ax, ax, fmaf(ay, ay, az * az));
        QXd[q] = pk2(-2.f * ax, -2.f * ax);
        QYd[q] = pk2(-2.f * ay, -2.f * ay);
        QZd[q] = pk2(-2.f * az, -2.f * az);
        X2d[q] = pk2(x2, x2);
        qmin[q] = 3.4e38f;
    }
    __syncthreads();

    const ulonglong2* P1 = (const ulonglong2*)sP;  // .x={x0,x1} .y={y0,y1}
    const ulonglong2* P2 = (const ulonglong2*)sQ;  // .x={z0,z1} .y={w0,w1}

    int b0 = lid & 1, b1 = (lid >> 1) & 1, b2 = (lid >> 2) & 1;

    for (int po = 0; po < TPR / 4; po++) {        // 16 windows
        float W[8];
        #pragma unroll
        for (int pi = 0; pi < 4; pi++) {          // 4 target pairs = 8 targets
            int p = po * 4 + pi;
            ulonglong2 t1 = P1[p];
            ulonglong2 t2 = P2[p];
            float T0, T1;
            #pragma unroll
            for (int q = 0; q < 8; q++) {
                uint64_t acc = add2(t2.y, X2d[q]);        // {w0+x2, w1+x2}
                acc = fma2(QZd[q], t2.x, acc);
                acc = fma2(QYd[q], t1.y, acc);
                acc = fma2(QXd[q], t1.x, acc);            // full distances
                float d0, d1;
                unpk(acc, d0, d1);
                qmin[q] = fminf(qmin[q], d0);             // q-side running mins
                qmin[q] = fminf(qmin[q], d1);
                T0 = (q == 0) ? d0 : fminf(T0, d0);       // t-side chains
                T1 = (q == 0) ? d1 : fminf(T1, d1);
            }
            W[2 * pi]     = T0;                           // target po*8 + 2pi
            W[2 * pi + 1] = T1;                           // target po*8 + 2pi+1
        }
        // 9-shfl butterfly: after C, lane holds target (lane&7); D/E finish.
        float R0 = bfold(W[0], W[1], b0, 1);
        float R1 = bfold(W[2], W[3], b0, 1);
        float R2 = bfold(W[4], W[5], b0, 1);
        float R3 = bfold(W[6], W[7], b0, 1);
        float S0 = bfold(R0, R1, b1, 2);
        float S1 = bfold(R2, R3, b1, 2);
        float U  = bfold(S0, S1, b2, 4);
        U = fminf(U, __shfl_xor_sync(0xFFFFFFFFu, U, 8));
        U = fminf(U, __shfl_xor_sync(0xFFFFFFFFu, U, 16));
        if (lid < 8) sWT[wid][po * 8 + lid] = U;
    }

    // q-side: REDG.MIN on bit patterns (exact & idempotent -> deterministic).
    int qg = b * NPTS + threadIdx.x;
    #pragma unroll
    for (int q = 0; q < 8; q++)
        atomicMin(&g_minq[qg + q * TPB], __float_as_uint(qmin[q]));

    // t-side: fold the 16 warp rows, plain store (unique owner per target).
    __syncthreads();
    if (threadIdx.x < TSL) {
        int p = threadIdx.x;
        float v = sWT[0][p];
        #pragma unroll
        for (int w = 1; w < NWARP; w++) v = fminf(v, sWT[w][p]);
        g_minq[NPTS * BB + b * NPTS + tc * TSL + p] = __float_as_uint(v);
    }

    // Ticket: last block sums everything.
    __threadfence();
    __syncthreads();
    __shared__ int amLast;
    if (threadIdx.x == 0) {
        int prev = atomicAdd(&g_ticket, 1);
        amLast = (prev == NBLK1 - 1);
    }
    __syncthreads();
    if (!amLast) return;

    __threadfence();   // acquire: all blocks' writes visible
    float sum = 0.f;
    const uint4* G = (const uint4*)g_minq;            // 8192 uint4
    #pragma unroll
    for (int jj = 0; jj < NQ_TOTAL / 4 / TPB; jj++) { // 16 iters
        uint4 u = __ldcg(&G[threadIdx.x + jj * TPB]);
        sum += (__uint_as_float(u.x) + __uint_as_float(u.y))
             + (__uint_as_float(u.z) + __uint_as_float(u.w));
    }
    #pragma unroll
    for (int off = 16; off > 0; off >>= 1)
        sum += __shfl_down_sync(0xFFFFFFFFu, sum, off);

    __shared__ float ws[TPB / 32];
    if ((threadIdx.x & 31) == 0) ws[threadIdx.x >> 5] = sum;
    __syncthreads();
    if (threadIdx.x == 0) {
        float tot = 0.f;
        #pragma unroll
        for (int i = 0; i < TPB / 32; i++) tot += ws[i];   // fixed order
        out[0] = tot * (1.0f / (float)(BB * NPTS));
        g_ticket = 0;                                      // reset for replay
    }
}

extern "C" void kernel_launch(void* const* d_in, const int* in_sizes, int n_in,
                              void* d_out, int out_size)
{
    const float* src = (const float*)d_in[0];
    const float* tgt = (const float*)d_in[1];
    float* out = (float*)d_out;

    void* minq_addr = nullptr;
    cudaGetSymbolAddress(&minq_addr, g_minq);
    // 0x7F7F7F7F = 3.39e38f sentinel for the REDG.MIN half.
    cudaMemsetAsync(minq_addr, 0x7F, NQ_TOTAL * sizeof(unsigned));

    chamfer_sym<<<NBLK1, TPB>>>(src, tgt, out);
}

// round 12
// speedup vs baseline: 1.2478x; 1.0114x over previous
#include <cuda_runtime.h>
#include <cstdint>

#define BB       4
#define NPTS     4096
#define TPB      1024
#define NWARP    (TPB / 32)               // 32
#define QPT      4                        // register queries per thread
#define NSLICE   32                       // target slices per batch
#define TSL      (NPTS / NSLICE)          // 128 targets per slice
#define TPR      (TSL / 2)                // 64 target pairs in smem
#define NBLK1    (BB * NSLICE)            // 128 blocks, 1/SM, 8 warps/SMSP
#define NQ_TOTAL (2 * BB * NPTS)          // 32768 min slots (16384 src + 16384 tgt)

// Running mins as float BIT PATTERNS (distances >= 0 -> uint order == float
// order). [0,16384): source-side (REDG.MIN, touched by 32 blocks).
// [16384,32768): target-side (plain STG, each owned by exactly 1 block).
__device__ unsigned g_minq[NQ_TOTAL];     // 128 KB
__device__ int      g_ticket;             // zero-init; last block resets it

__device__ __forceinline__ uint64_t pk2(float lo, float hi) {
    uint64_t r;
    asm("mov.b64 %0, {%1, %2};" : "=l"(r) : "f"(lo), "f"(hi));
    return r;
}
__device__ __forceinline__ uint64_t fma2(uint64_t a, uint64_t b, uint64_t c) {
    uint64_t d;
    asm("fma.rn.f32x2 %0, %1, %2, %3;" : "=l"(d) : "l"(a), "l"(b), "l"(c));
    return d;
}
__device__ __forceinline__ uint64_t add2(uint64_t a, uint64_t b) {
    uint64_t d;
    asm("add.rn.f32x2 %0, %1, %2;" : "=l"(d) : "l"(a), "l"(b));
    return d;
}
__device__ __forceinline__ void unpk(uint64_t v, float& lo, float& hi) {
    asm("mov.b64 {%0, %1}, %2;" : "=f"(lo), "=f"(hi) : "l"(v));
}
// Butterfly fold step: lane keeps (sel ? odd : even), gives the other away;
// the xor-delta partner does the mirror image.
__device__ __forceinline__ float bfold(float even, float odd, int sel, int delta) {
    float give = sel ? even : odd;
    float recv = __shfl_xor_sync(0xFFFFFFFFu, give, delta);
    float keep = sel ? odd : even;
    return fminf(keep, recv);
}

// SYMMETRIC kernel: each distance computed ONCE, feeds BOTH direction mins.
// TPB=1024, 4 register queries/thread (32 regs of packs) -> <=64 regs ->
// 8 warps/SMSP for latency hiding. Targets PAIR-PACKED in smem:
// sP[p]={x0,x1,y0,y1}, sQ[p]={z0,z1,w0,w1} (w=|t|^2). Per target-pair step:
//   2 LDS.128 + (4 queries x [1 ADD2 + 3 FFMA2]) -> 8 full distances
//   + 8 FMNMX q-side mins + 4-deep t-side chains (alu pipe).
// t-side flush per 8-target window: 9-shfl butterfly -> lane&7 holds the
// warp-min -> sWT -> cross-warp fold. Min is exact => order-independent.
__global__ void __launch_bounds__(TPB, 1)
chamfer_sym(const float* __restrict__ src, const float* __restrict__ tgt,
            float* __restrict__ out)
{
    __shared__ float4 sP[TPR];            // {x0,x1,y0,y1}
    __shared__ float4 sQ[TPR];            // {z0,z1,w0,w1}
    __shared__ float  sWT[NWARP][TSL];    // per-warp t-side partial mins (16 KB)

    int b   = blockIdx.x >> 5;
    int tc  = blockIdx.x & 31;
    int wid = threadIdx.x >> 5, lid = threadIdx.x & 31;

    const float* qb = src + (size_t)b * NPTS * 3;
    const float* db = tgt + ((size_t)b * NPTS + tc * TSL) * 3;

    if (threadIdx.x < TPR) {
        int p = threadIdx.x;
        const float* t = db + 6 * p;
        float x0 = t[0], y0 = t[1], z0 = t[2];
        float x1 = t[3], y1 = t[4], z1 = t[5];
        sP[p] = make_float4(x0, x1, y0, y1);
        sQ[p] = make_float4(z0, z1,
                            fmaf(x0, x0, fmaf(y0, y0, z0 * z0)),
                            fmaf(x1, x1, fmaf(y1, y1, z1 * z1)));
    }

    // 4 register queries, duplicated packs (32 regs).
    uint64_t QXd[QPT], QYd[QPT], QZd[QPT], X2d[QPT];
    float qmin[QPT];
    #pragma unroll
    for (int q = 0; q < QPT; q++) {
        int qa = threadIdx.x + q * TPB;
        float ax = qb[3 * qa], ay = qb[3 * qa + 1], az = qb[3 * qa + 2];
        float x2 = fmaf(ax, ax, fmaf(ay, ay, az * az));
        QXd[q] = pk2(-2.f * ax, -2.f * ax);
        QYd[q] = pk2(-2.f * ay, -2.f * ay);
        QZd[q] = pk2(-2.f * az, -2.f * az);
        X2d[q] = pk2(x2, x2);
        qmin[q] = 3.4e38f;
    }
    __syncthreads();

    const ulonglong2* P1 = (const ulonglong2*)sP;  // .x={x0,x1} .y={y0,y1}
    const ulonglong2* P2 = (const ulonglong2*)sQ;  // .x={z0,z1} .y={w0,w1}

    int b0 = lid & 1, b1 = (lid >> 1) & 1, b2 = (lid >> 2) & 1;

    for (int po = 0; po < TPR / 4; po++) {        // 16 windows
        float W[8];
        #pragma unroll
        for (int pi = 0; pi < 4; pi++) {          // 4 target pairs = 8 targets
            int p = po * 4 + pi;
            ulonglong2 t1 = P1[p];
            ulonglong2 t2 = P2[p];
            float T0, T1;
            #pragma unroll
            for (int q = 0; q < QPT; q++) {
                uint64_t acc = add2(t2.y, X2d[q]);        // {w0+x2, w1+x2}
                acc = fma2(QZd[q], t2.x, acc);
                acc = fma2(QYd[q], t1.y, acc);
                acc = fma2(QXd[q], t1.x, acc);            // full distances
                float d0, d1;
                unpk(acc, d0, d1);
                qmin[q] = fminf(qmin[q], d0);             // q-side running mins
                qmin[q] = fminf(qmin[q], d1);
                T0 = (q == 0) ? d0 : fminf(T0, d0);       // t-side chains
                T1 = (q == 0) ? d1 : fminf(T1, d1);
            }
            W[2 * pi]     = T0;                           // target po*8 + 2pi
            W[2 * pi + 1] = T1;                           // target po*8 + 2pi+1
        }
        // 9-shfl butterfly: after xor 1/2/4, lane holds target (lane&7).
        float R0 = bfold(W[0], W[1], b0, 1);
        float R1 = bfold(W[2], W[3], b0, 1);
        float R2 = bfold(W[4], W[5], b0, 1);
        float R3 = bfold(W[6], W[7], b0, 1);
        float S0 = bfold(R0, R1, b1, 2);
        float S1 = bfold(R2, R3, b1, 2);
        float U  = bfold(S0, S1, b2, 4);
        U = fminf(U, __shfl_xor_sync(0xFFFFFFFFu, U, 8));
        U = fminf(U, __shfl_xor_sync(0xFFFFFFFFu, U, 16));
        if (lid < 8) sWT[wid][po * 8 + lid] = U;
    }

    // q-side: REDG.MIN on bit patterns (exact & idempotent -> deterministic).
    int qg = b * NPTS + threadIdx.x;
    #pragma unroll
    for (int q = 0; q < QPT; q++)
        atomicMin(&g_minq[qg + q * TPB], __float_as_uint(qmin[q]));

    // t-side: fold the 32 warp rows, plain store (unique owner per target).
    __syncthreads();
    if (threadIdx.x < TSL) {
        int p = threadIdx.x;
        float v = sWT[0][p];
        #pragma unroll
        for (int w = 1; w < NWARP; w++) v = fminf(v, sWT[w][p]);
        g_minq[NPTS * BB + b * NPTS + tc * TSL + p] = __float_as_uint(v);
    }

    // Ticket: last block sums everything.
    __threadfence();
    __syncthreads();
    __shared__ int amLast;
    if (threadIdx.x == 0) {
        int prev = atomicAdd(&g_ticket, 1);
        amLast = (prev == NBLK1 - 1);
    }
    __syncthreads();
    if (!amLast) return;

    __threadfence();   // acquire: all blocks' writes visible
    float sum = 0.f;
    const uint4* G = (const uint4*)g_minq;            // 8192 uint4
    #pragma unroll
    for (int jj = 0; jj < NQ_TOTAL / 4 / TPB; jj++) { // 8 iters
        uint4 u = __ldcg(&G[threadIdx.x + jj * TPB]);
        sum += (__uint_as_float(u.x) + __uint_as_float(u.y))
             + (__uint_as_float(u.z) + __uint_as_float(u.w));
    }
    #pragma unroll
    for (int off = 16; off > 0; off >>= 1)
        sum += __shfl_down_sync(0xFFFFFFFFu, sum, off);

    __shared__ float ws[NWARP];
    if ((threadIdx.x & 31) == 0) ws[threadIdx.x >> 5] = sum;
    __syncthreads();
    if (threadIdx.x == 0) {
        float tot = 0.f;
        #pragma unroll
        for (int i = 0; i < NWARP; i++) tot += ws[i];      // fixed order
        out[0] = tot * (1.0f / (float)(BB * NPTS));
        g_ticket = 0;                                      // reset for replay
    }
}

extern "C" void kernel_launch(void* const* d_in, const int* in_sizes, int n_in,
                              void* d_out, int out_size)
{
    const float* src = (const float*)d_in[0];
    const float* tgt = (const float*)d_in[1];
    float* out = (float*)d_out;

    void* minq_addr = nullptr;
    cudaGetSymbolAddress(&minq_addr, g_minq);
    // 0x7F7F7F7F = 3.39e38f sentinel for the REDG.MIN half.
    cudaMemsetAsync(minq_addr, 0x7F, NQ_TOTAL * sizeof(unsigned));

    chamfer_sym<<<NBLK1, TPB>>>(src, tgt, out);
}